// round 1
// baseline (speedup 1.0000x reference)
#include <cuda_runtime.h>
#include <math.h>

// ---------------------------------------------------------------------------
// E64AdditiveHCell: out_t = h_t * silu(h_t),
//   h_t = alpha_t * h_{t-1} + (1-alpha_t) * tanh(h_{t-1} + Wx x_t + b)
//   alpha_t = sigmoid(Wa x_t + ba)
// Phase 1: one fused GEMM pass computes sigmoid(X @ Wa^T + ba) and X @ Wx^T + b
//          for all timesteps (X read once).
// Phase 2: 8192 independent per-(b,d) recurrence chains, fully parallel.
// ---------------------------------------------------------------------------

#define BM 64
#define BN 64
#define BK 32
#define PAD 4  // keeps 16B alignment of smem rows (stride 68 floats = 272B)

// Scratch (static device arrays: allocation-guard safe). 64 MB each.
#define MAX_M 16384
#define MAX_N 1024
__device__ float g_alpha[(size_t)MAX_M * MAX_N];
__device__ float g_wx[(size_t)MAX_M * MAX_N];

__global__ __launch_bounds__(256)
void gemm2_fused_kernel(const float* __restrict__ X,
                        const float* __restrict__ Wa,
                        const float* __restrict__ Wx,
                        const float* __restrict__ ba,
                        const float* __restrict__ bb,
                        int M, int N, int K)
{
    __shared__ __align__(16) float As [BK][BM + PAD];
    __shared__ __align__(16) float BsA[BK][BN + PAD];
    __shared__ __align__(16) float BsW[BK][BN + PAD];

    const int t  = threadIdx.x;
    const int tx = t & 15;          // column group (n)
    const int ty = t >> 4;          // row group (m)
    const int m0 = blockIdx.y * BM;
    const int n0 = blockIdx.x * BN;

    const int lr = t >> 3;          // 0..31  (tile row for global loads)
    const int lc = (t & 7) * 4;     // 0,4,...,28 (k offset, float4)

    float accA[4][4];
    float accW[4][4];
#pragma unroll
    for (int i = 0; i < 4; i++)
#pragma unroll
        for (int j = 0; j < 4; j++) { accA[i][j] = 0.f; accW[i][j] = 0.f; }

    for (int k0 = 0; k0 < K; k0 += BK) {
        // Stage global -> registers
        float4 a0 = *(const float4*)&X [(size_t)(m0 + lr     ) * K + k0 + lc];
        float4 a1 = *(const float4*)&X [(size_t)(m0 + lr + 32) * K + k0 + lc];
        float4 c0 = *(const float4*)&Wa[(size_t)(n0 + lr     ) * K + k0 + lc];
        float4 c1 = *(const float4*)&Wa[(size_t)(n0 + lr + 32) * K + k0 + lc];
        float4 d0 = *(const float4*)&Wx[(size_t)(n0 + lr     ) * K + k0 + lc];
        float4 d1 = *(const float4*)&Wx[(size_t)(n0 + lr + 32) * K + k0 + lc];

        __syncthreads();  // previous tile fully consumed

        // Transposed store: smem is [k][m] / [k][n] so inner loop reads float4
        {
            float va0[4] = {a0.x, a0.y, a0.z, a0.w};
            float va1[4] = {a1.x, a1.y, a1.z, a1.w};
            float vc0[4] = {c0.x, c0.y, c0.z, c0.w};
            float vc1[4] = {c1.x, c1.y, c1.z, c1.w};
            float vd0[4] = {d0.x, d0.y, d0.z, d0.w};
            float vd1[4] = {d1.x, d1.y, d1.z, d1.w};
#pragma unroll
            for (int q = 0; q < 4; q++) {
                As [lc + q][lr     ] = va0[q];
                As [lc + q][lr + 32] = va1[q];
                BsA[lc + q][lr     ] = vc0[q];
                BsA[lc + q][lr + 32] = vc1[q];
                BsW[lc + q][lr     ] = vd0[q];
                BsW[lc + q][lr + 32] = vd1[q];
            }
        }
        __syncthreads();

#pragma unroll
        for (int kk = 0; kk < BK; kk++) {
            float4 av  = *(const float4*)&As [kk][ty * 4];
            float4 bav = *(const float4*)&BsA[kk][tx * 4];
            float4 bwv = *(const float4*)&BsW[kk][tx * 4];
            float a[4]  = {av.x,  av.y,  av.z,  av.w };
            float bA[4] = {bav.x, bav.y, bav.z, bav.w};
            float bW[4] = {bwv.x, bwv.y, bwv.z, bwv.w};
#pragma unroll
            for (int i = 0; i < 4; i++)
#pragma unroll
                for (int j = 0; j < 4; j++) {
                    accA[i][j] = fmaf(a[i], bA[j], accA[i][j]);
                    accW[i][j] = fmaf(a[i], bW[j], accW[i][j]);
                }
        }
    }

    // Epilogue: bias + sigmoid for alpha; bias for wx. Coalesced float4 stores.
    const int ncol = n0 + tx * 4;
    float biasA[4], biasW[4];
#pragma unroll
    for (int j = 0; j < 4; j++) { biasA[j] = ba[ncol + j]; biasW[j] = bb[ncol + j]; }

#pragma unroll
    for (int i = 0; i < 4; i++) {
        const int row = m0 + ty * 4 + i;
        float4 va, vw;
        float sA[4], sW[4];
#pragma unroll
        for (int j = 0; j < 4; j++) {
            float pre = accA[i][j] + biasA[j];
            sA[j] = 1.0f / (1.0f + expf(-pre));
            sW[j] = accW[i][j] + biasW[j];
        }
        va.x = sA[0]; va.y = sA[1]; va.z = sA[2]; va.w = sA[3];
        vw.x = sW[0]; vw.y = sW[1]; vw.z = sW[2]; vw.w = sW[3];
        *(float4*)&g_alpha[(size_t)row * N + ncol] = va;
        *(float4*)&g_wx  [(size_t)row * N + ncol] = vw;
    }
}

// ---------------------------------------------------------------------------
// Recurrence: 8192 independent chains, 8-deep load prefetch for MLP.
// ---------------------------------------------------------------------------
__global__ __launch_bounds__(128)
void recur_kernel(const float* __restrict__ h0,
                  float* __restrict__ out,   // [T, B*D]
                  float* __restrict__ hout,  // [T+1, B*D]
                  int T, int BD)
{
    const int idx = blockIdx.x * blockDim.x + threadIdx.x;
    if (idx >= BD) return;

    float h = h0[idx];
    hout[idx] = h;

    const float* ga = g_alpha + idx;
    const float* gw = g_wx + idx;

    const int U = 8;
    for (int tt = 0; tt < T; tt += U) {
        float a[U], w[U];
#pragma unroll
        for (int u = 0; u < U; u++) {
            size_t o = (size_t)(tt + u) * BD;
            a[u] = ga[o];
            w[u] = gw[o];
        }
#pragma unroll
        for (int u = 0; u < U; u++) {
            float v = tanhf(h + w[u]);
            h = fmaf(a[u], h, (1.0f - a[u]) * v);
            float sig = 1.0f / (1.0f + expf(-h));
            size_t o = (size_t)(tt + u) * BD + idx;
            out[o] = h * h * sig;          // h * silu(h)
            hout[o + BD] = h;              // h[t+1]
        }
    }
}

extern "C" void kernel_launch(void* const* d_in, const int* in_sizes, int n_in,
                              void* d_out, int out_size)
{
    const float* x  = (const float*)d_in[0];  // [T,B,D]
    const float* h0 = (const float*)d_in[1];  // [B,D]
    const float* Wa = (const float*)d_in[2];  // [D,D]
    const float* ba = (const float*)d_in[3];  // [D]
    const float* Wx = (const float*)d_in[4];  // [D,D]
    const float* bb = (const float*)d_in[5];  // [D]

    const int BD = in_sizes[1];              // B*D = 8192
    const int D  = in_sizes[3];              // 1024
    const int M  = in_sizes[0] / D;          // T*B = 16384
    const int T  = in_sizes[0] / BD;         // 2048
    const int N  = D, K = D;

    float* out  = (float*)d_out;                     // [T,B,D]
    float* hout = (float*)d_out + (size_t)T * BD;    // [T+1,B,D]

    dim3 grid(N / BN, M / BM);   // (16, 256)
    gemm2_fused_kernel<<<grid, 256>>>(x, Wa, Wx, ba, bb, M, N, K);

    int threads = 128;
    int blocks  = (BD + threads - 1) / threads;      // 64 blocks
    recur_kernel<<<blocks, threads>>>(h0, out, hout, T, BD);
}

// round 2
// speedup vs baseline: 2.5639x; 2.5639x over previous
#include <cuda_runtime.h>
#include <math.h>
#include <stdint.h>

// ---------------------------------------------------------------------------
// E64AdditiveHCell
// Phase 1: fused tensor-core (mma.sync tf32) GEMM pass computes, for all t:
//   alpha = sigmoid(X @ Wa^T + ba)   and   wx = X @ Wx^T + b
//   stored interleaved as float2 {alpha, wx} scratch.
// Phase 2: 8192 independent recurrence chains (latency-optimized).
// ---------------------------------------------------------------------------

#define BM 128
#define BN 128
#define BK 32
#define KST 36                 // padded row stride in floats (bank = 4g+tid -> conflict-free)
#define NKS (1024 / BK)        // 32 k-steps (K fixed = 1024 for this problem family)

#define MAX_T 2048
#define MAX_BD 8192
__device__ float2 g_aw[(size_t)MAX_T * MAX_BD];   // [T*B, D] interleaved (alpha, wx)

// ---------------- PTX helpers ----------------
__device__ __forceinline__ unsigned f2tf32(float x) {
    unsigned r;
    asm("cvt.rna.tf32.f32 %0, %1;" : "=r"(r) : "f"(x));
    return r;
}

__device__ __forceinline__ void mma_tf32(float c[4], const unsigned a[4], const unsigned b[2]) {
    asm volatile(
        "mma.sync.aligned.m16n8k8.row.col.f32.tf32.tf32.f32 "
        "{%0,%1,%2,%3},{%4,%5,%6,%7},{%8,%9},{%0,%1,%2,%3};"
        : "+f"(c[0]), "+f"(c[1]), "+f"(c[2]), "+f"(c[3])
        : "r"(a[0]), "r"(a[1]), "r"(a[2]), "r"(a[3]), "r"(b[0]), "r"(b[1]));
}

__device__ __forceinline__ void cp16(uint32_t dst, const void* src) {
    asm volatile("cp.async.cg.shared.global [%0], [%1], 16;" :: "r"(dst), "l"(src));
}
__device__ __forceinline__ void cp_commit() { asm volatile("cp.async.commit_group;"); }
__device__ __forceinline__ void cp_wait0()  { asm volatile("cp.async.wait_group 0;" ::: "memory"); }

// ---------------------------------------------------------------------------
// Fused dual GEMM: 256 threads, warp grid 2(m) x 4(n), warp tile 64x32 per W.
// ---------------------------------------------------------------------------
extern __shared__ float smem_dyn[];

__global__ void __launch_bounds__(256, 1)
gemm2_tc(const float* __restrict__ X,  const float* __restrict__ Wa,
         const float* __restrict__ Wx, const float* __restrict__ ba,
         const float* __restrict__ bb, int M, int N, int K)
{
    const int t    = threadIdx.x;
    const int lane = t & 31;
    const int warp = t >> 5;
    const int g    = lane >> 2;     // groupID 0..7
    const int tid4 = lane & 3;      // 0..3
    const int wm   = warp >> 2;     // 0..1
    const int wn   = warp & 3;      // 0..3
    const int m0   = blockIdx.y * BM;
    const int n0   = blockIdx.x * BN;

    float accA[4][4][4];
    float accW[4][4][4];
#pragma unroll
    for (int mi = 0; mi < 4; mi++)
#pragma unroll
        for (int ni = 0; ni < 4; ni++)
#pragma unroll
            for (int r = 0; r < 4; r++) { accA[mi][ni][r] = 0.f; accW[mi][ni][r] = 0.f; }

    // global staging map: each thread copies 4 float4 per matrix per k-step
    const int row_l = t >> 3;       // 0..31 (+32*i)
    const int q_l   = t & 7;        // float4 index within 32-float k-slab

    const int TILE_F  = BM * KST;           // floats per matrix tile
    const int BUF_F   = 3 * TILE_F;         // floats per buffer
    uint32_t s_u32 = (uint32_t)__cvta_generic_to_shared(smem_dyn);

    const float* Xb  = X  + (size_t)m0 * K;
    const float* Wab = Wa + (size_t)n0 * K;
    const float* Wxb = Wx + (size_t)n0 * K;

    auto issue = [&](int ks, int buf) {
        const size_t kof = (size_t)ks * BK + (size_t)q_l * 4;
        uint32_t d = s_u32 + (uint32_t)(buf * BUF_F) * 4u;
#pragma unroll
        for (int i = 0; i < 4; i++) {
            int r = row_l + 32 * i;
            uint32_t so = (uint32_t)(r * KST + q_l * 4) * 4u;
            cp16(d + so,                          Xb  + (size_t)r * K + kof);
            cp16(d + (uint32_t)TILE_F * 4u + so,  Wab + (size_t)r * K + kof);
            cp16(d + (uint32_t)TILE_F * 8u + so,  Wxb + (size_t)r * K + kof);
        }
        cp_commit();
    };

    issue(0, 0);

    int buf = 0;
    for (int ks = 0; ks < NKS; ks++) {
        cp_wait0();
        __syncthreads();
        if (ks + 1 < NKS) issue(ks + 1, buf ^ 1);

        const float* sX = smem_dyn + buf * BUF_F;
        const float* sA = sX + TILE_F;
        const float* sW = sA + TILE_F;

#pragma unroll
        for (int kk = 0; kk < BK / 8; kk++) {
            const int k = kk * 8 + tid4;
            unsigned af[4][4];
#pragma unroll
            for (int mi = 0; mi < 4; mi++) {
                const int m = wm * 64 + mi * 16 + g;
                af[mi][0] = f2tf32(sX[m       * KST + k]);
                af[mi][1] = f2tf32(sX[(m + 8) * KST + k]);
                af[mi][2] = f2tf32(sX[m       * KST + k + 4]);
                af[mi][3] = f2tf32(sX[(m + 8) * KST + k + 4]);
            }
            unsigned bfA[4][2], bfW[4][2];
#pragma unroll
            for (int ni = 0; ni < 4; ni++) {
                const int n = wn * 32 + ni * 8 + g;
                bfA[ni][0] = f2tf32(sA[n * KST + k]);
                bfA[ni][1] = f2tf32(sA[n * KST + k + 4]);
                bfW[ni][0] = f2tf32(sW[n * KST + k]);
                bfW[ni][1] = f2tf32(sW[n * KST + k + 4]);
            }
#pragma unroll
            for (int mi = 0; mi < 4; mi++)
#pragma unroll
                for (int ni = 0; ni < 4; ni++) {
                    mma_tf32(accA[mi][ni], af[mi], bfA[ni]);
                    mma_tf32(accW[mi][ni], af[mi], bfW[ni]);
                }
        }
        buf ^= 1;
    }

    // Epilogue: bias + sigmoid(alpha), interleaved float2 scratch, float4 stores
#pragma unroll
    for (int ni = 0; ni < 4; ni++) {
        const int col0 = n0 + wn * 32 + ni * 8 + 2 * tid4;
        const float ba0 = ba[col0], ba1 = ba[col0 + 1];
        const float bb0 = bb[col0], bb1 = bb[col0 + 1];
#pragma unroll
        for (int mi = 0; mi < 4; mi++) {
            const int row0 = m0 + wm * 64 + mi * 16 + g;
            {
                float pa0 = accA[mi][ni][0] + ba0;
                float pa1 = accA[mi][ni][1] + ba1;
                float4 v;
                v.x = 1.0f / (1.0f + expf(-pa0));
                v.y = accW[mi][ni][0] + bb0;
                v.z = 1.0f / (1.0f + expf(-pa1));
                v.w = accW[mi][ni][1] + bb1;
                *(float4*)&g_aw[(size_t)row0 * N + col0] = v;
            }
            {
                float pa2 = accA[mi][ni][2] + ba0;
                float pa3 = accA[mi][ni][3] + ba1;
                float4 v;
                v.x = 1.0f / (1.0f + expf(-pa2));
                v.y = accW[mi][ni][2] + bb0;
                v.z = 1.0f / (1.0f + expf(-pa3));
                v.w = accW[mi][ni][3] + bb1;
                *(float4*)&g_aw[(size_t)(row0 + 8) * N + col0] = v;
            }
        }
    }
}

// ---------------------------------------------------------------------------
// Recurrence: exp-based tanh (MUFU chain), 2-group-deep register prefetch.
// ---------------------------------------------------------------------------
__device__ __forceinline__ float fast_tanh(float s) {
    // tanh(s) = 1 - 2/(exp(2s)+1); saturates correctly at +-inf.
    float e = __expf(2.0f * s);
    float r = __frcp_rn(e + 1.0f);
    return fmaf(-2.0f, r, 1.0f);
}

__global__ void __launch_bounds__(128)
recur_kernel(const float* __restrict__ h0,
             float* __restrict__ out,   // [T, BD]
             float* __restrict__ hout,  // [T+1, BD]
             int T, int BD)
{
    const int idx = blockIdx.x * blockDim.x + threadIdx.x;
    if (idx >= BD) return;

    float h = h0[idx];
    hout[idx] = h;

    const float2* __restrict__ aw = g_aw + idx;

    float2 buf0[16], buf1[16];
#pragma unroll
    for (int u = 0; u < 16; u++) buf0[u] = aw[(size_t)u * BD];

    for (int tt = 0; tt < T; tt += 32) {
        // prefetch group tt+16
#pragma unroll
        for (int u = 0; u < 16; u++) buf1[u] = aw[(size_t)(tt + 16 + u) * BD];

        // compute group tt from buf0
#pragma unroll
        for (int u = 0; u < 16; u++) {
            const float a = buf0[u].x, w = buf0[u].y;
            float v = fast_tanh(h + w);
            h = fmaf(a, h - v, v);
            float sg = __frcp_rn(1.0f + __expf(-h));
            size_t o = (size_t)(tt + u) * BD + idx;
            out[o] = h * (h * sg);
            hout[o + BD] = h;
        }

        // prefetch group tt+32
        if (tt + 32 < T) {
#pragma unroll
            for (int u = 0; u < 16; u++) buf0[u] = aw[(size_t)(tt + 32 + u) * BD];
        }

        // compute group tt+16 from buf1
#pragma unroll
        for (int u = 0; u < 16; u++) {
            const float a = buf1[u].x, w = buf1[u].y;
            float v = fast_tanh(h + w);
            h = fmaf(a, h - v, v);
            float sg = __frcp_rn(1.0f + __expf(-h));
            size_t o = (size_t)(tt + 16 + u) * BD + idx;
            out[o] = h * (h * sg);
            hout[o + BD] = h;
        }
    }
}

// ---------------------------------------------------------------------------
extern "C" void kernel_launch(void* const* d_in, const int* in_sizes, int n_in,
                              void* d_out, int out_size)
{
    const float* x  = (const float*)d_in[0];  // [T,B,D]
    const float* h0 = (const float*)d_in[1];  // [B,D]
    const float* Wa = (const float*)d_in[2];  // [D,D]
    const float* ba = (const float*)d_in[3];  // [D]
    const float* Wx = (const float*)d_in[4];  // [D,D]
    const float* bb = (const float*)d_in[5];  // [D]

    const int BD = in_sizes[1];               // 8192
    const int D  = in_sizes[3];               // 1024
    const int M  = in_sizes[0] / D;           // 16384
    const int T  = in_sizes[0] / BD;           // 2048
    const int N  = D, K = D;

    float* out  = (float*)d_out;                    // [T,B,D]
    float* hout = (float*)d_out + (size_t)T * BD;   // [T+1,B,D]

    static int smem_set = 0;
    const int SMEM_BYTES = 2 * 3 * BM * KST * 4;    // 110592
    if (!smem_set) {
        cudaFuncSetAttribute(gemm2_tc, cudaFuncAttributeMaxDynamicSharedMemorySize, SMEM_BYTES);
        smem_set = 1;
    }

    dim3 grid(N / BN, M / BM);   // (8, 128)
    gemm2_tc<<<grid, 256, SMEM_BYTES>>>(x, Wa, Wx, ba, bb, M, N, K);

    recur_kernel<<<(BD + 127) / 128, 128>>>(h0, out, hout, T, BD);
}

// round 3
// speedup vs baseline: 3.2449x; 1.2656x over previous
#include <cuda_runtime.h>
#include <math.h>
#include <stdint.h>

// ---------------------------------------------------------------------------
// E64AdditiveHCell — 5-kernel pipeline:
//  1) prepass: round X, Wa, Wx to tf32 (rna) into scratch -> mainloop has no CVTs
//  2) fused dual tensor-core GEMM: alpha=sigmoid(X Wa^T + ba), wx = X Wx^T + b,
//     interleaved float2 scratch
//  3) recurrence over T (latency-optimized, h only)
//  4) elementwise out = h * silu(h) (massively parallel)
// ---------------------------------------------------------------------------

#define BM 128
#define BN 128
#define BK 32
#define KST 36
#define NKS (1024 / BK)

#define MAX_T 2048
#define MAX_BD 8192
#define MAX_M 16384
#define MAX_K 1024
__device__ float2 g_aw[(size_t)MAX_T * MAX_BD];       // {alpha, wx} per (t, b, d)
__device__ float  g_x [(size_t)MAX_M * MAX_K];        // tf32-rounded X
__device__ float  g_wa[(size_t)MAX_K * MAX_K];        // tf32-rounded Wa
__device__ float  g_wx[(size_t)MAX_K * MAX_K];        // tf32-rounded Wx

// ---------------- PTX helpers ----------------
__device__ __forceinline__ float tf32r(float x) {
    unsigned r;
    asm("cvt.rna.tf32.f32 %0, %1;" : "=r"(r) : "f"(x));
    return __uint_as_float(r);
}
__device__ __forceinline__ float ex2f(float x) {
    float r;
    asm("ex2.approx.ftz.f32 %0, %1;" : "=f"(r) : "f"(x));
    return r;
}
__device__ __forceinline__ float rcpf(float x) {
    float r;
    asm("rcp.approx.ftz.f32 %0, %1;" : "=f"(r) : "f"(x));
    return r;
}
__device__ __forceinline__ float fast_sigmoid(float x) {
    // 1/(1+e^-x) = 1/(1+2^(-x*log2e))
    return rcpf(1.0f + ex2f(-1.4426950408889634f * x));
}

__device__ __forceinline__ void mma_tf32(float c[4], const unsigned a[4], const unsigned b[2]) {
    asm volatile(
        "mma.sync.aligned.m16n8k8.row.col.f32.tf32.tf32.f32 "
        "{%0,%1,%2,%3},{%4,%5,%6,%7},{%8,%9},{%0,%1,%2,%3};"
        : "+f"(c[0]), "+f"(c[1]), "+f"(c[2]), "+f"(c[3])
        : "r"(a[0]), "r"(a[1]), "r"(a[2]), "r"(a[3]), "r"(b[0]), "r"(b[1]));
}
__device__ __forceinline__ void cp16(uint32_t dst, const void* src) {
    asm volatile("cp.async.cg.shared.global [%0], [%1], 16;" :: "r"(dst), "l"(src));
}
__device__ __forceinline__ void cp_commit() { asm volatile("cp.async.commit_group;"); }
__device__ __forceinline__ void cp_wait0()  { asm volatile("cp.async.wait_group 0;" ::: "memory"); }

// ---------------------------------------------------------------------------
// 1) tf32 rounding prepass (vectorized, pure bandwidth)
// ---------------------------------------------------------------------------
__global__ void __launch_bounds__(256)
round_tf32_kernel(const float* __restrict__ src, float* __restrict__ dst, int n4)
{
    int i = blockIdx.x * blockDim.x + threadIdx.x;
    if (i >= n4) return;
    float4 v = ((const float4*)src)[i];
    v.x = tf32r(v.x); v.y = tf32r(v.y); v.z = tf32r(v.z); v.w = tf32r(v.w);
    ((float4*)dst)[i] = v;
}

// ---------------------------------------------------------------------------
// 2) Fused dual GEMM: 256 threads, warp grid 2(m) x 4(n), warp tile 64x32/W.
//    Operands pre-rounded -> no CVT in mainloop.
// ---------------------------------------------------------------------------
extern __shared__ float smem_dyn[];

__global__ void __launch_bounds__(256, 1)
gemm2_tc(const float* __restrict__ X,  const float* __restrict__ Wa,
         const float* __restrict__ Wx, const float* __restrict__ ba,
         const float* __restrict__ bb, int M, int N, int K)
{
    const int t    = threadIdx.x;
    const int lane = t & 31;
    const int warp = t >> 5;
    const int g    = lane >> 2;
    const int tid4 = lane & 3;
    const int wm   = warp >> 2;
    const int wn   = warp & 3;
    const int m0   = blockIdx.y * BM;
    const int n0   = blockIdx.x * BN;

    float accA[4][4][4];
    float accW[4][4][4];
#pragma unroll
    for (int mi = 0; mi < 4; mi++)
#pragma unroll
        for (int ni = 0; ni < 4; ni++)
#pragma unroll
            for (int r = 0; r < 4; r++) { accA[mi][ni][r] = 0.f; accW[mi][ni][r] = 0.f; }

    const int row_l = t >> 3;
    const int q_l   = t & 7;

    const int TILE_F = BM * KST;
    const int BUF_F  = 3 * TILE_F;
    uint32_t s_u32 = (uint32_t)__cvta_generic_to_shared(smem_dyn);

    const float* Xb  = X  + (size_t)m0 * K;
    const float* Wab = Wa + (size_t)n0 * K;
    const float* Wxb = Wx + (size_t)n0 * K;

    auto issue = [&](int ks, int buf) {
        const size_t kof = (size_t)ks * BK + (size_t)q_l * 4;
        uint32_t d = s_u32 + (uint32_t)(buf * BUF_F) * 4u;
#pragma unroll
        for (int i = 0; i < 4; i++) {
            int r = row_l + 32 * i;
            uint32_t so = (uint32_t)(r * KST + q_l * 4) * 4u;
            cp16(d + so,                          Xb  + (size_t)r * K + kof);
            cp16(d + (uint32_t)TILE_F * 4u + so,  Wab + (size_t)r * K + kof);
            cp16(d + (uint32_t)TILE_F * 8u + so,  Wxb + (size_t)r * K + kof);
        }
        cp_commit();
    };

    issue(0, 0);

    int buf = 0;
    for (int ks = 0; ks < NKS; ks++) {
        cp_wait0();
        __syncthreads();
        if (ks + 1 < NKS) issue(ks + 1, buf ^ 1);

        const float* sX = smem_dyn + buf * BUF_F;
        const float* sA = sX + TILE_F;
        const float* sW = sA + TILE_F;

#pragma unroll
        for (int kk = 0; kk < BK / 8; kk++) {
            const int k = kk * 8 + tid4;
            unsigned af[4][4];
#pragma unroll
            for (int mi = 0; mi < 4; mi++) {
                const int m = wm * 64 + mi * 16 + g;
                af[mi][0] = __float_as_uint(sX[m       * KST + k]);
                af[mi][1] = __float_as_uint(sX[(m + 8) * KST + k]);
                af[mi][2] = __float_as_uint(sX[m       * KST + k + 4]);
                af[mi][3] = __float_as_uint(sX[(m + 8) * KST + k + 4]);
            }
            unsigned bfA[4][2], bfW[4][2];
#pragma unroll
            for (int ni = 0; ni < 4; ni++) {
                const int n = wn * 32 + ni * 8 + g;
                bfA[ni][0] = __float_as_uint(sA[n * KST + k]);
                bfA[ni][1] = __float_as_uint(sA[n * KST + k + 4]);
                bfW[ni][0] = __float_as_uint(sW[n * KST + k]);
                bfW[ni][1] = __float_as_uint(sW[n * KST + k + 4]);
            }
#pragma unroll
            for (int mi = 0; mi < 4; mi++)
#pragma unroll
                for (int ni = 0; ni < 4; ni++) {
                    mma_tf32(accA[mi][ni], af[mi], bfA[ni]);
                    mma_tf32(accW[mi][ni], af[mi], bfW[ni]);
                }
        }
        buf ^= 1;
    }

    // Epilogue: bias + fast sigmoid(alpha), interleaved float2, float4 stores
#pragma unroll
    for (int ni = 0; ni < 4; ni++) {
        const int col0 = n0 + wn * 32 + ni * 8 + 2 * tid4;
        const float ba0 = ba[col0], ba1 = ba[col0 + 1];
        const float bb0 = bb[col0], bb1 = bb[col0 + 1];
#pragma unroll
        for (int mi = 0; mi < 4; mi++) {
            const int row0 = m0 + wm * 64 + mi * 16 + g;
            {
                float4 v;
                v.x = fast_sigmoid(accA[mi][ni][0] + ba0);
                v.y = accW[mi][ni][0] + bb0;
                v.z = fast_sigmoid(accA[mi][ni][1] + ba1);
                v.w = accW[mi][ni][1] + bb1;
                *(float4*)&g_aw[(size_t)row0 * N + col0] = v;
            }
            {
                float4 v;
                v.x = fast_sigmoid(accA[mi][ni][2] + ba0);
                v.y = accW[mi][ni][2] + bb0;
                v.z = fast_sigmoid(accA[mi][ni][3] + ba1);
                v.w = accW[mi][ni][3] + bb1;
                *(float4*)&g_aw[(size_t)(row0 + 8) * N + col0] = v;
            }
        }
    }
}

// ---------------------------------------------------------------------------
// 3) Recurrence: h only. Critical path per step:
//    t = fma(h,C,w') -> ex2 -> add1 -> rcp.approx -> fma(q,r,t2)  (~44 cyc)
//    with w' = w*C, p = 1-a, q = 2a-2, t2 = fma(a,h,p) all off-path.
// ---------------------------------------------------------------------------
__global__ void __launch_bounds__(64)
recur_kernel(const float* __restrict__ h0,
             float* __restrict__ hout,  // [T+1, BD]
             int T, int BD)
{
    const int idx = blockIdx.x * blockDim.x + threadIdx.x;
    if (idx >= BD) return;

    const float C = 2.8853900817779268f;  // 2*log2(e)

    float h = h0[idx];
    hout[idx] = h;

    const float2* __restrict__ aw = g_aw + idx;
    float* __restrict__ hw = hout + BD + idx;

    float2 buf0[16], buf1[16];
#pragma unroll
    for (int u = 0; u < 16; u++) buf0[u] = aw[(size_t)u * BD];

    for (int tt = 0; tt < T; tt += 32) {
#pragma unroll
        for (int u = 0; u < 16; u++) buf1[u] = aw[(size_t)(tt + 16 + u) * BD];

#pragma unroll
        for (int u = 0; u < 16; u++) {
            const float a = buf0[u].x;
            const float wp = buf0[u].y * C;      // off-path
            const float p = 1.0f - a;            // off-path
            const float q = -2.0f * p;           // off-path
            float tv = fmaf(h, C, wp);
            float e  = ex2f(tv);
            float r  = rcpf(e + 1.0f);
            float t2 = fmaf(a, h, p);            // parallel to ex2/rcp chain
            h = fmaf(q, r, t2);
            hw[(size_t)(tt + u) * BD] = h;
        }

        if (tt + 32 < T) {
#pragma unroll
            for (int u = 0; u < 16; u++) buf0[u] = aw[(size_t)(tt + 32 + u) * BD];
        }

#pragma unroll
        for (int u = 0; u < 16; u++) {
            const float a = buf1[u].x;
            const float wp = buf1[u].y * C;
            const float p = 1.0f - a;
            const float q = -2.0f * p;
            float tv = fmaf(h, C, wp);
            float e  = ex2f(tv);
            float r  = rcpf(e + 1.0f);
            float t2 = fmaf(a, h, p);
            h = fmaf(q, r, t2);
            hw[(size_t)(tt + 16 + u) * BD] = h;
        }
    }
}

// ---------------------------------------------------------------------------
// 4) out = h * silu(h) = h^2 * sigmoid(h), reading hout[t+1]. Pure bandwidth.
// ---------------------------------------------------------------------------
__global__ void __launch_bounds__(256)
out_kernel(const float* __restrict__ hsrc, float* __restrict__ out, int n4)
{
    int i = blockIdx.x * blockDim.x + threadIdx.x;
    if (i >= n4) return;
    float4 v = ((const float4*)hsrc)[i];
    float4 o;
    o.x = v.x * v.x * fast_sigmoid(v.x);
    o.y = v.y * v.y * fast_sigmoid(v.y);
    o.z = v.z * v.z * fast_sigmoid(v.z);
    o.w = v.w * v.w * fast_sigmoid(v.w);
    ((float4*)out)[i] = o;
}

// ---------------------------------------------------------------------------
extern "C" void kernel_launch(void* const* d_in, const int* in_sizes, int n_in,
                              void* d_out, int out_size)
{
    const float* x  = (const float*)d_in[0];  // [T,B,D]
    const float* h0 = (const float*)d_in[1];  // [B,D]
    const float* Wa = (const float*)d_in[2];  // [D,D]
    const float* ba = (const float*)d_in[3];  // [D]
    const float* Wx = (const float*)d_in[4];  // [D,D]
    const float* bb = (const float*)d_in[5];  // [D]

    const int BD = in_sizes[1];               // 8192
    const int D  = in_sizes[3];               // 1024
    const int M  = in_sizes[0] / D;           // 16384
    const int T  = in_sizes[0] / BD;          // 2048
    const int N  = D, K = D;

    float* out  = (float*)d_out;                    // [T,B,D]
    float* hout = (float*)d_out + (size_t)T * BD;   // [T+1,B,D]

    float* gx;  cudaGetSymbolAddress((void**)&gx,  g_x);
    float* gwa; cudaGetSymbolAddress((void**)&gwa, g_wa);
    float* gwx; cudaGetSymbolAddress((void**)&gwx, g_wx);

    // 1) tf32 prepass
    {
        int nx4 = (M * K) / 4;
        int nw4 = (K * K) / 4;
        round_tf32_kernel<<<(nx4 + 255) / 256, 256>>>(x,  gx,  nx4);
        round_tf32_kernel<<<(nw4 + 255) / 256, 256>>>(Wa, gwa, nw4);
        round_tf32_kernel<<<(nw4 + 255) / 256, 256>>>(Wx, gwx, nw4);
    }

    // 2) fused dual GEMM
    const int SMEM_BYTES = 2 * 3 * BM * KST * 4;    // 110592
    cudaFuncSetAttribute(gemm2_tc, cudaFuncAttributeMaxDynamicSharedMemorySize, SMEM_BYTES);
    dim3 grid(N / BN, M / BM);   // (8, 128)
    gemm2_tc<<<grid, 256, SMEM_BYTES>>>(gx, gwa, gwx, ba, bb, M, N, K);

    // 3) recurrence (h only)
    recur_kernel<<<(BD + 63) / 64, 64>>>(h0, hout, T, BD);

    // 4) out = h * silu(h)
    int no4 = (T * BD) / 4;
    out_kernel<<<(no4 + 255) / 256, 256>>>(hout + BD, out, no4);
}

// round 5
// speedup vs baseline: 4.4106x; 1.3592x over previous
#include <cuda_runtime.h>
#include <cuda_fp16.h>
#include <math.h>
#include <stdint.h>

// ---------------------------------------------------------------------------
// E64AdditiveHCell — fp16 mma.sync edition (tcgen05 ISA unavailable: harness
// compiles at target sm_103 without the 'a' feature set).
//  1) prepass: convert X, Wa, Wx to fp16 (rn)
//  2) dual fp16 tensor-core GEMM (m16n8k16, fp32 accum), 4-stage cp.async:
//     alpha = sigmoid(X Wa^T + ba), wx = X Wx^T + b  -> interleaved float2
//  3) recurrence over T (tanh.approx, ~28-cyc critical path)
//  4) out = h * silu(h)
// ---------------------------------------------------------------------------

#define BM 128
#define BN 128
#define NKS 32                 // K stages: 1024 / 32
#define NSTG 4
#define HST_B 80               // smem row stride in bytes (40 halves)
#define A_BYTES (128 * HST_B)  // 10240
#define STG_BYTES (3 * A_BYTES)
#define A_OFF  0
#define BA_OFF A_BYTES
#define BW_OFF (2 * A_BYTES)

#define MAX_T 2048
#define MAX_BD 8192
#define MAX_M 16384
#define MAX_K 1024
__device__ float2 g_aw[(size_t)MAX_T * MAX_BD];     // {alpha, wx}
__device__ __half g_x [(size_t)MAX_M * MAX_K];
__device__ __half g_wa[(size_t)MAX_K * MAX_K];
__device__ __half g_wx[(size_t)MAX_K * MAX_K];

// ---------------- helpers ----------------
__device__ __forceinline__ float ex2f(float x) {
    float r; asm("ex2.approx.ftz.f32 %0, %1;" : "=f"(r) : "f"(x)); return r;
}
__device__ __forceinline__ float rcpf(float x) {
    float r; asm("rcp.approx.ftz.f32 %0, %1;" : "=f"(r) : "f"(x)); return r;
}
__device__ __forceinline__ float tanhx(float x) {
    float r; asm("tanh.approx.f32 %0, %1;" : "=f"(r) : "f"(x)); return r;
}
__device__ __forceinline__ float fast_sigmoid(float x) {
    return rcpf(1.0f + ex2f(-1.4426950408889634f * x));
}
__device__ __forceinline__ void mma_f16(float c[4], const uint32_t a[4], const uint32_t b[2]) {
    asm volatile(
        "mma.sync.aligned.m16n8k16.row.col.f32.f16.f16.f32 "
        "{%0,%1,%2,%3},{%4,%5,%6,%7},{%8,%9},{%0,%1,%2,%3};"
        : "+f"(c[0]), "+f"(c[1]), "+f"(c[2]), "+f"(c[3])
        : "r"(a[0]), "r"(a[1]), "r"(a[2]), "r"(a[3]), "r"(b[0]), "r"(b[1]));
}
__device__ __forceinline__ void cp16(uint32_t dst, const void* src) {
    asm volatile("cp.async.cg.shared.global [%0], [%1], 16;" :: "r"(dst), "l"(src));
}
__device__ __forceinline__ void cp_commit() { asm volatile("cp.async.commit_group;"); }
__device__ __forceinline__ void cp_wait0()  { asm volatile("cp.async.wait_group 0;" ::: "memory"); }
__device__ __forceinline__ void cp_wait1()  { asm volatile("cp.async.wait_group 1;" ::: "memory"); }
__device__ __forceinline__ void cp_wait2()  { asm volatile("cp.async.wait_group 2;" ::: "memory"); }

// ---------------------------------------------------------------------------
// 1) fp32 -> fp16 prepass
// ---------------------------------------------------------------------------
__global__ void __launch_bounds__(256)
f2h_kernel(const float* __restrict__ src, __half* __restrict__ dst, int n4)
{
    int i = blockIdx.x * blockDim.x + threadIdx.x;
    if (i >= n4) return;
    float4 v = ((const float4*)src)[i];
    __half2 h0 = __floats2half2_rn(v.x, v.y);
    __half2 h1 = __floats2half2_rn(v.z, v.w);
    uint2 o;
    o.x = *(uint32_t*)&h0;
    o.y = *(uint32_t*)&h1;
    ((uint2*)dst)[i] = o;
}

// ---------------------------------------------------------------------------
// 2) fused dual fp16 GEMM: 256 threads, warps 2(m) x 4(n), warp tile 64x32/W
// ---------------------------------------------------------------------------
extern __shared__ __align__(128) char smem_raw[];

__global__ void __launch_bounds__(256, 1)
gemm2_f16(const __half* __restrict__ X,  const __half* __restrict__ Wa,
          const __half* __restrict__ Wx, const float* __restrict__ ba,
          const float* __restrict__ bb)
{
    __shared__ float s_ba[BN], s_bb[BN];

    const int t    = threadIdx.x;
    const int lane = t & 31;
    const int warp = t >> 5;
    const int g    = lane >> 2;
    const int tid4 = lane & 3;
    const int wm   = warp >> 2;
    const int wn   = warp & 3;
    const int m0   = blockIdx.y * BM;
    const int n0   = blockIdx.x * BN;

    uint32_t dyn_u32 = (uint32_t)__cvta_generic_to_shared(smem_raw);

    if (t < BN) { s_ba[t] = ba[n0 + t]; s_bb[t] = bb[n0 + t]; }

    float accA[4][4][4];
    float accW[4][4][4];
#pragma unroll
    for (int mi = 0; mi < 4; mi++)
#pragma unroll
        for (int ni = 0; ni < 4; ni++)
#pragma unroll
            for (int r = 0; r < 4; r++) { accA[mi][ni][r] = 0.f; accW[mi][ni][r] = 0.f; }

    const __half* Xb  = X  + (size_t)m0 * MAX_K;
    const __half* Wab = Wa + (size_t)n0 * MAX_K;
    const __half* Wxb = Wx + (size_t)n0 * MAX_K;

    auto issue = [&](int ks, int b) {
        uint32_t dbase = dyn_u32 + (uint32_t)b * STG_BYTES;
        const size_t kof = (size_t)ks * 32;    // halves
#pragma unroll
        for (int i = 0; i < 2; i++) {
            int ch  = i * 256 + t;             // 512 chunks of 16B per matrix
            int row = ch >> 2, q = ch & 3;
            uint32_t so = (uint32_t)(row * HST_B + q * 16);
            size_t go = (size_t)row * MAX_K + kof + (size_t)q * 8;
            cp16(dbase + A_OFF  + so, Xb  + go);
            cp16(dbase + BA_OFF + so, Wab + go);
            cp16(dbase + BW_OFF + so, Wxb + go);
        }
        cp_commit();
    };

    issue(0, 0); issue(1, 1); issue(2, 2);

    for (int c = 0; c < NKS; c++) {
        const int stg = c & 3;
        if (c < NKS - 2)      cp_wait2();
        else if (c == NKS - 2) cp_wait1();
        else                   cp_wait0();
        __syncthreads();
        if (c + 3 < NKS) issue(c + 3, (c + 3) & 3);

        const char* base = smem_raw + (size_t)stg * STG_BYTES;
        const char* sX = base + A_OFF;
        const char* sA = base + BA_OFF;
        const char* sW = base + BW_OFF;

#pragma unroll
        for (int kk = 0; kk < 2; kk++) {
            const int kb = kk * 32 + tid4 * 4;     // byte offset of first half2
            uint32_t af[4][4];
#pragma unroll
            for (int mi = 0; mi < 4; mi++) {
                const int m = wm * 64 + mi * 16 + g;
                af[mi][0] = *(const uint32_t*)(sX + m       * HST_B + kb);
                af[mi][1] = *(const uint32_t*)(sX + (m + 8) * HST_B + kb);
                af[mi][2] = *(const uint32_t*)(sX + m       * HST_B + kb + 16);
                af[mi][3] = *(const uint32_t*)(sX + (m + 8) * HST_B + kb + 16);
            }
            uint32_t bfA[4][2], bfW[4][2];
#pragma unroll
            for (int ni = 0; ni < 4; ni++) {
                const int n = wn * 32 + ni * 8 + g;
                bfA[ni][0] = *(const uint32_t*)(sA + n * HST_B + kb);
                bfA[ni][1] = *(const uint32_t*)(sA + n * HST_B + kb + 16);
                bfW[ni][0] = *(const uint32_t*)(sW + n * HST_B + kb);
                bfW[ni][1] = *(const uint32_t*)(sW + n * HST_B + kb + 16);
            }
#pragma unroll
            for (int mi = 0; mi < 4; mi++)
#pragma unroll
                for (int ni = 0; ni < 4; ni++) {
                    mma_f16(accA[mi][ni], af[mi], bfA[ni]);
                    mma_f16(accW[mi][ni], af[mi], bfW[ni]);
                }
        }
    }
    __syncthreads();

    // Epilogue: bias + fast sigmoid(alpha), interleaved float2 scratch
#pragma unroll
    for (int ni = 0; ni < 4; ni++) {
        const int col0 = n0 + wn * 32 + ni * 8 + 2 * tid4;
        const float ba0 = s_ba[col0 - n0], ba1 = s_ba[col0 - n0 + 1];
        const float bb0 = s_bb[col0 - n0], bb1 = s_bb[col0 - n0 + 1];
#pragma unroll
        for (int mi = 0; mi < 4; mi++) {
            const int row0 = m0 + wm * 64 + mi * 16 + g;
            {
                float4 v;
                v.x = fast_sigmoid(accA[mi][ni][0] + ba0);
                v.y = accW[mi][ni][0] + bb0;
                v.z = fast_sigmoid(accA[mi][ni][1] + ba1);
                v.w = accW[mi][ni][1] + bb1;
                *(float4*)&g_aw[(size_t)row0 * MAX_K + col0] = v;
            }
            {
                float4 v;
                v.x = fast_sigmoid(accA[mi][ni][2] + ba0);
                v.y = accW[mi][ni][2] + bb0;
                v.z = fast_sigmoid(accA[mi][ni][3] + ba1);
                v.w = accW[mi][ni][3] + bb1;
                *(float4*)&g_aw[(size_t)(row0 + 8) * MAX_K + col0] = v;
            }
        }
    }
}

// ---------------------------------------------------------------------------
// 3) Recurrence: tanh.approx, 2-deep prefetch, 32-thread blocks over 148 SMs
// ---------------------------------------------------------------------------
__global__ void __launch_bounds__(32)
recur_kernel(const float* __restrict__ h0,
             float* __restrict__ hout,  // [T+1, BD]
             int T, int BD)
{
    const int idx = blockIdx.x * blockDim.x + threadIdx.x;
    if (idx >= BD) return;

    float h = h0[idx];
    hout[idx] = h;

    const float2* __restrict__ aw = g_aw + idx;
    float* __restrict__ hw = hout + BD + idx;

    float2 buf0[16], buf1[16];
#pragma unroll
    for (int u = 0; u < 16; u++) buf0[u] = aw[(size_t)u * BD];

    for (int tt = 0; tt < T; tt += 32) {
#pragma unroll
        for (int u = 0; u < 16; u++) buf1[u] = aw[(size_t)(tt + 16 + u) * BD];
#pragma unroll
        for (int u = 0; u < 16; u++) {
            const float a = buf0[u].x, w = buf0[u].y;
            float v = tanhx(h + w);
            h = fmaf(a, h - v, v);
            hw[(size_t)(tt + u) * BD] = h;
        }
        if (tt + 32 < T) {
#pragma unroll
            for (int u = 0; u < 16; u++) buf0[u] = aw[(size_t)(tt + 32 + u) * BD];
        }
#pragma unroll
        for (int u = 0; u < 16; u++) {
            const float a = buf1[u].x, w = buf1[u].y;
            float v = tanhx(h + w);
            h = fmaf(a, h - v, v);
            hw[(size_t)(tt + 16 + u) * BD] = h;
        }
    }
}

// ---------------------------------------------------------------------------
// 4) out = h^2 * sigmoid(h)
// ---------------------------------------------------------------------------
__global__ void __launch_bounds__(256)
out_kernel(const float* __restrict__ hsrc, float* __restrict__ out, int n4)
{
    int i = blockIdx.x * blockDim.x + threadIdx.x;
    if (i >= n4) return;
    float4 v = ((const float4*)hsrc)[i];
    float4 o;
    o.x = v.x * v.x * fast_sigmoid(v.x);
    o.y = v.y * v.y * fast_sigmoid(v.y);
    o.z = v.z * v.z * fast_sigmoid(v.z);
    o.w = v.w * v.w * fast_sigmoid(v.w);
    ((float4*)out)[i] = o;
}

// ---------------------------------------------------------------------------
extern "C" void kernel_launch(void* const* d_in, const int* in_sizes, int n_in,
                              void* d_out, int out_size)
{
    const float* x  = (const float*)d_in[0];
    const float* h0 = (const float*)d_in[1];
    const float* Wa = (const float*)d_in[2];
    const float* ba = (const float*)d_in[3];
    const float* Wx = (const float*)d_in[4];
    const float* bb = (const float*)d_in[5];

    const int BD = in_sizes[1];               // 8192
    const int D  = in_sizes[3];               // 1024
    const int M  = in_sizes[0] / D;           // 16384
    const int T  = in_sizes[0] / BD;          // 2048

    float* out  = (float*)d_out;
    float* hout = (float*)d_out + (size_t)T * BD;

    __half* gx;  cudaGetSymbolAddress((void**)&gx,  g_x);
    __half* gwa; cudaGetSymbolAddress((void**)&gwa, g_wa);
    __half* gwx; cudaGetSymbolAddress((void**)&gwx, g_wx);

    // 1) fp16 prepass
    {
        int nx4 = (M * D) / 4;
        int nw4 = (D * D) / 4;
        f2h_kernel<<<(nx4 + 255) / 256, 256>>>(x,  gx,  nx4);
        f2h_kernel<<<(nw4 + 255) / 256, 256>>>(Wa, gwa, nw4);
        f2h_kernel<<<(nw4 + 255) / 256, 256>>>(Wx, gwx, nw4);
    }

    // 2) dual fp16 GEMM
    const int SMEM_BYTES = NSTG * STG_BYTES;        // 122880
    cudaFuncSetAttribute(gemm2_f16, cudaFuncAttributeMaxDynamicSharedMemorySize, SMEM_BYTES);
    dim3 grid(D / BN, M / BM);   // (8, 128) = 1024 CTAs
    gemm2_f16<<<grid, 256, SMEM_BYTES>>>(gx, gwa, gwx, ba, bb);

    // 3) recurrence
    recur_kernel<<<(BD + 31) / 32, 32>>>(h0, hout, T, BD);

    // 4) out
    int no4 = (T * BD) / 4;
    out_kernel<<<(no4 + 255) / 256, 256>>>(hout + BD, out, no4);
}